// round 4
// baseline (speedup 1.0000x reference)
#include <cuda_runtime.h>
#include <cuda_bf16.h>

#define Bn 256
#define Ln 1024
#define En 128
#define Hn 256
#define Vn 64

// ---- device-global scratch (no allocations allowed) ----
__device__ float g_proj[Vn * Hn];                    // token -> x_proj row (b_e folded in)
__device__ float g_hout[(size_t)Bn * Ln * Hn];       // all hidden states, 268MB
__device__ int   g_x_is32;

// ---------------- f32x2 helpers (Blackwell packed fp32) ----------------
__device__ __forceinline__ void ffma2(unsigned long long& acc,
                                      unsigned long long a, unsigned long long b) {
    asm("fma.rn.f32x2 %0, %1, %2, %0;" : "+l"(acc) : "l"(a), "l"(b));
}
__device__ __forceinline__ unsigned long long fadd2(unsigned long long a,
                                                    unsigned long long b) {
    unsigned long long r;
    asm("add.rn.f32x2 %0, %1, %2;" : "=l"(r) : "l"(a), "l"(b));
    return r;
}
__device__ __forceinline__ unsigned long long pack2u(unsigned int lo, unsigned int hi) {
    unsigned long long r;
    asm("mov.b64 %0, {%1, %2};" : "=l"(r) : "r"(lo), "r"(hi));
    return r;
}
__device__ __forceinline__ float2 unpack2(unsigned long long v) {
    unsigned int lo, hi;
    asm("mov.b64 {%0, %1}, %2;" : "=r"(lo), "=r"(hi) : "l"(v));
    return make_float2(__uint_as_float(lo), __uint_as_float(hi));
}
// expand bf16x2 reg (k0 lo | k1 hi) into f32x2 pair (k0, k1)
__device__ __forceinline__ unsigned long long wpair(unsigned int w) {
    return pack2u(w << 16, w & 0xffff0000u);
}
__device__ __forceinline__ float tanh_fast(float x) {
    float e = __expf(x + x);
    return 1.0f - __fdividef(2.0f, e + 1.0f);
}

// ---------------- dtype detection ----------------
__global__ void k_reset() { g_x_is32 = 0; }

__global__ void k_detect(const unsigned int* __restrict__ xw) {
    int i = blockIdx.x * blockDim.x + threadIdx.x;
    int idx = 2 * i + 1;                 // odd 32-bit words
    if (idx < Bn * Ln) {
        if (xw[idx] != 0u) g_x_is32 = 1; // int64 high halves are all zero (vals 0..63)
    }
}

// ---------------- projection table ----------------
// proj[v][h] = sum_e emb[v][e] * W_e[h][e] + b_e[h]
__global__ void k_proj(const float* __restrict__ emb, const float* __restrict__ We,
                       const float* __restrict__ be) {
    __shared__ float es[En];
    int v = blockIdx.x, j = threadIdx.x;
    if (j < En) es[j] = emb[v * En + j];
    __syncthreads();
    float acc = 0.f;
    #pragma unroll
    for (int e = 0; e < En; e++) acc = fmaf(es[e], We[j * En + e], acc);
    g_proj[v * Hn + j] = acc + be[j];
}

// ---------------- recurrence ----------------
// 128 CTAs x 512 threads. CTA owns batches (2c, 2c+1) for the full 1024-step chain.
// Split-k: thread pair (2j, 2j+1) shares output j; thread kh = tid&1 covers
// k in [kh*128, kh*128+128). Each thread's 128 W values live in 64 bf16x2
// REGISTERS (no smem W, no spill). Packed fma.rn.f32x2 throughout; cross-half
// reduction via one shfl_xor. After the reduction, thread kh owns batch kh
// for tanh + stores.
__global__ void __launch_bounds__(512, 1) k_rnn(const void* __restrict__ xraw,
        const float* __restrict__ hidden, const float* __restrict__ Wh,
        const float* __restrict__ bh, float* __restrict__ dout, int write_final) {
    __shared__ __align__(16) float hs[2][2][Hn];     // [buf][batch][256]
    const int tid = threadIdx.x;
    const int j  = tid >> 1;          // output index 0..255
    const int kh = tid & 1;           // k-half 0/1; also my batch after reduce
    const int b0 = 2 * blockIdx.x;
    const int myb = b0 + kh;
    const int is32 = g_x_is32;
    const int* x32       = (const int*)xraw;
    const long long* x64 = (const long long*)xraw;

    // load my half W_h row into registers (64 bf16x2 words)
    unsigned int wreg[64];
    const float4* Wh4 = (const float4*)Wh;
    #pragma unroll
    for (int q = 0; q < 32; q++) {
        float4 w4 = Wh4[j * 64 + kh * 32 + q];
        __nv_bfloat162 lo2 = __floats2bfloat162_rn(w4.x, w4.y);
        __nv_bfloat162 hi2 = __floats2bfloat162_rn(w4.z, w4.w);
        wreg[2 * q]     = *(unsigned int*)&lo2;
        wreg[2 * q + 1] = *(unsigned int*)&hi2;
    }

    hs[0][kh][j] = hidden[myb * Hn + j];
    const float bhj = bh[j];
    __syncthreads();

    float fin = 0.f;
    for (int t = 0; t < Ln; t++) {
        const int cur = t & 1;
        // prefetch token + x_proj early (latency hidden under the matvec)
        int tok  = is32 ? x32[myb * Ln + t] : (int)x64[myb * Ln + t];
        float xp = g_proj[tok * Hn + j];

        const ulonglong2* h0 = (const ulonglong2*)(&hs[cur][0][kh * 128]);
        const ulonglong2* h1 = (const ulonglong2*)(&hs[cur][1][kh * 128]);

        unsigned long long a00 = 0ull, a01 = 0ull, a10 = 0ull, a11 = 0ull;
        #pragma unroll
        for (int q = 0; q < 32; q++) {
            unsigned long long wp0 = wpair(wreg[2 * q]);       // (w[4q],   w[4q+1])
            unsigned long long wp1 = wpair(wreg[2 * q + 1]);   // (w[4q+2], w[4q+3])
            ulonglong2 p0 = h0[q];                             // batch0 h pairs (broadcast)
            ulonglong2 p1 = h1[q];                             // batch1
            ffma2(a00, wp0, p0.x); ffma2(a01, wp1, p0.y);
            ffma2(a10, wp0, p1.x); ffma2(a11, wp1, p1.y);
        }
        float2 s0 = unpack2(fadd2(a00, a01));   // batch0 partial (this k-half)
        float2 s1 = unpack2(fadd2(a10, a11));   // batch1 partial
        float p0 = s0.x + s0.y;
        float p1 = s1.x + s1.y;
        // combine k-halves across the thread pair
        p0 += __shfl_xor_sync(0xffffffffu, p0, 1);
        p1 += __shfl_xor_sync(0xffffffffu, p1, 1);
        float myp = kh ? p1 : p0;               // full dot for my batch
        float nh = tanh_fast(myp + xp + bhj);

        g_hout[((size_t)myb * Ln + t) * Hn + j] = nh;
        hs[cur ^ 1][kh][j] = nh;
        fin = nh;
        __syncthreads();
    }
    if (write_final) {
        dout[(size_t)Bn * Ln * Vn + myb * Hn + j] = fin;
    }
}

// ---------------- logits GEMM ----------------
// logits[r][v] = sum_k hout[r][k] * fcw[v][k] + fcb[v]
// Persistent grid; fcw^T resident in smem; 64-row tiles; 4x4 register blocking.
#define LOG_SMEM (65536 + 64 * 260 * 4)

__global__ void __launch_bounds__(256, 1) k_logits(const float* __restrict__ fcw,
        const float* __restrict__ fcb, float* __restrict__ out) {
    extern __shared__ char smem[];
    float* fT  = (float*)smem;              // [256][64]  fT[k][v] = fcw[v][k]
    float* hsm = (float*)(smem + 65536);    // [64][260]
    const int tid = threadIdx.x;
    const int tx = tid & 15, ty = tid >> 4;

    for (int p = tid; p < Vn * Hn; p += 256) {   // conflict-free transposed fill
        int v = p & 63, k = p >> 6;
        fT[k * 64 + v] = fcw[v * Hn + k];
    }
    float4 bias = *(const float4*)(fcb + 4 * tx);
    __syncthreads();

    const int ntiles = (Bn * Ln) / 64;      // 4096
    for (int tile = blockIdx.x; tile < ntiles; tile += gridDim.x) {
        const float4* src = (const float4*)(g_hout + (size_t)tile * 64 * Hn);
        for (int p = tid; p < 64 * 64; p += 256) {
            int row = p >> 6, kc = p & 63;
            *(float4*)(hsm + row * 260 + 4 * kc) = src[p];
        }
        __syncthreads();

        float acc[4][4];
        #pragma unroll
        for (int r = 0; r < 4; r++)
            #pragma unroll
            for (int c = 0; c < 4; c++) acc[r][c] = 0.f;

        #pragma unroll 8
        for (int k = 0; k < Hn; k++) {
            float4 b4 = *(const float4*)(fT + k * 64 + 4 * tx);
            float a0 = hsm[(4 * ty + 0) * 260 + k];
            float a1 = hsm[(4 * ty + 1) * 260 + k];
            float a2 = hsm[(4 * ty + 2) * 260 + k];
            float a3 = hsm[(4 * ty + 3) * 260 + k];
            acc[0][0] = fmaf(a0, b4.x, acc[0][0]); acc[0][1] = fmaf(a0, b4.y, acc[0][1]);
            acc[0][2] = fmaf(a0, b4.z, acc[0][2]); acc[0][3] = fmaf(a0, b4.w, acc[0][3]);
            acc[1][0] = fmaf(a1, b4.x, acc[1][0]); acc[1][1] = fmaf(a1, b4.y, acc[1][1]);
            acc[1][2] = fmaf(a1, b4.z, acc[1][2]); acc[1][3] = fmaf(a1, b4.w, acc[1][3]);
            acc[2][0] = fmaf(a2, b4.x, acc[2][0]); acc[2][1] = fmaf(a2, b4.y, acc[2][1]);
            acc[2][2] = fmaf(a2, b4.z, acc[2][2]); acc[2][3] = fmaf(a2, b4.w, acc[2][3]);
            acc[3][0] = fmaf(a3, b4.x, acc[3][0]); acc[3][1] = fmaf(a3, b4.y, acc[3][1]);
            acc[3][2] = fmaf(a3, b4.z, acc[3][2]); acc[3][3] = fmaf(a3, b4.w, acc[3][3]);
        }
        #pragma unroll
        for (int r = 0; r < 4; r++) {
            float4 o;
            o.x = acc[r][0] + bias.x; o.y = acc[r][1] + bias.y;
            o.z = acc[r][2] + bias.z; o.w = acc[r][3] + bias.w;
            *(float4*)(out + ((size_t)tile * 64 + 4 * ty + r) * 64 + 4 * tx) = o;
        }
        __syncthreads();
    }
}

// ---------------- launch ----------------
extern "C" void kernel_launch(void* const* d_in, const int* in_sizes, int n_in,
                              void* d_out, int out_size) {
    const void*  x      = d_in[0];
    const float* hidden = (const float*)d_in[1];
    const float* emb    = (const float*)d_in[2];
    const float* We     = (const float*)d_in[3];
    const float* be     = (const float*)d_in[4];
    const float* Wh     = (const float*)d_in[5];
    const float* bhp    = (const float*)d_in[6];
    const float* fcw    = (const float*)d_in[7];
    const float* fcb    = (const float*)d_in[8];
    float* out = (float*)d_out;

    cudaFuncSetAttribute(k_logits, cudaFuncAttributeMaxDynamicSharedMemorySize, LOG_SMEM);

    k_reset<<<1, 1>>>();
    k_detect<<<(Bn * Ln / 2 + 255) / 256, 256>>>((const unsigned int*)x);
    k_proj<<<Vn, Hn>>>(emb, We, be);

    int write_final = (out_size >= Bn * Ln * Vn + Bn * Hn) ? 1 : 0;
    k_rnn<<<Bn / 2, 512>>>(x, hidden, Wh, bhp, out, write_final);
    k_logits<<<148, 256, LOG_SMEM>>>(fcw, fcb, out);
}

// round 5
// speedup vs baseline: 1.0051x; 1.0051x over previous
#include <cuda_runtime.h>
#include <cuda_bf16.h>

#define Bn 256
#define Ln 1024
#define En 128
#define Hn 256
#define Vn 64

// ---- device-global scratch (no allocations allowed) ----
__device__ float g_proj[Vn * Hn];                    // token -> x_proj row (b_e folded in)
__device__ float g_hout[(size_t)Bn * Ln * Hn];       // all hidden states, 268MB
__device__ int   g_x_is32;

// ---------------- f32x2 helpers (Blackwell packed fp32) ----------------
__device__ __forceinline__ void ffma2(unsigned long long& acc,
                                      unsigned long long a, unsigned long long b) {
    asm("fma.rn.f32x2 %0, %1, %2, %0;" : "+l"(acc) : "l"(a), "l"(b));
}
__device__ __forceinline__ unsigned long long fadd2(unsigned long long a,
                                                    unsigned long long b) {
    unsigned long long r;
    asm("add.rn.f32x2 %0, %1, %2;" : "=l"(r) : "l"(a), "l"(b));
    return r;
}
__device__ __forceinline__ unsigned long long pack2u(unsigned int lo, unsigned int hi) {
    unsigned long long r;
    asm("mov.b64 %0, {%1, %2};" : "=l"(r) : "r"(lo), "r"(hi));
    return r;
}
__device__ __forceinline__ float2 unpack2(unsigned long long v) {
    unsigned int lo, hi;
    asm("mov.b64 {%0, %1}, %2;" : "=r"(lo), "=r"(hi) : "l"(v));
    return make_float2(__uint_as_float(lo), __uint_as_float(hi));
}
// expand bf16x2 reg (k0 lo | k1 hi) into f32x2 pair (k0, k1)
__device__ __forceinline__ unsigned long long wpair(unsigned int w) {
    return pack2u(w << 16, w & 0xffff0000u);
}
__device__ __forceinline__ float tanh_fast(float x) {
    float e = __expf(x + x);
    return 1.0f - __fdividef(2.0f, e + 1.0f);
}

// ---------------- dtype detection ----------------
__global__ void k_reset() { g_x_is32 = 0; }

__global__ void k_detect(const unsigned int* __restrict__ xw) {
    int i = blockIdx.x * blockDim.x + threadIdx.x;
    int idx = 2 * i + 1;                 // odd 32-bit words
    if (idx < Bn * Ln) {
        if (xw[idx] != 0u) g_x_is32 = 1; // int64 high halves are all zero (vals 0..63)
    }
}

// ---------------- projection table ----------------
// proj[v][h] = sum_e emb[v][e] * W_e[h][e] + b_e[h]
__global__ void k_proj(const float* __restrict__ emb, const float* __restrict__ We,
                       const float* __restrict__ be) {
    __shared__ float es[En];
    int v = blockIdx.x, j = threadIdx.x;
    if (j < En) es[j] = emb[v * En + j];
    __syncthreads();
    float acc = 0.f;
    #pragma unroll
    for (int e = 0; e < En; e++) acc = fmaf(es[e], We[j * En + e], acc);
    g_proj[v * Hn + j] = acc + be[j];
}

// ---------------- recurrence ----------------
// 128 CTAs x 512 threads. CTA owns batches (2c, 2c+1) for the full 1024-step chain.
// Split-k: thread pair (2j, 2j+1) shares output j; thread kh = tid&1 covers
// k in [kh*128, kh*128+128). Each thread's 128 W values live in 64 bf16x2
// REGISTERS (no smem W, no spill). Packed fma.rn.f32x2 throughout; cross-half
// reduction via one shfl_xor. After the reduction, thread kh owns batch kh
// for tanh + stores.
__global__ void __launch_bounds__(512, 1) k_rnn(const void* __restrict__ xraw,
        const float* __restrict__ hidden, const float* __restrict__ Wh,
        const float* __restrict__ bh, float* __restrict__ dout, int write_final) {
    __shared__ __align__(16) float hs[2][2][Hn];     // [buf][batch][256]
    const int tid = threadIdx.x;
    const int j  = tid >> 1;          // output index 0..255
    const int kh = tid & 1;           // k-half 0/1; also my batch after reduce
    const int b0 = 2 * blockIdx.x;
    const int myb = b0 + kh;
    const int is32 = g_x_is32;
    const int* x32       = (const int*)xraw;
    const long long* x64 = (const long long*)xraw;

    // load my half W_h row into registers (64 bf16x2 words)
    unsigned int wreg[64];
    const float4* Wh4 = (const float4*)Wh;
    #pragma unroll
    for (int q = 0; q < 32; q++) {
        float4 w4 = Wh4[j * 64 + kh * 32 + q];
        __nv_bfloat162 lo2 = __floats2bfloat162_rn(w4.x, w4.y);
        __nv_bfloat162 hi2 = __floats2bfloat162_rn(w4.z, w4.w);
        wreg[2 * q]     = *(unsigned int*)&lo2;
        wreg[2 * q + 1] = *(unsigned int*)&hi2;
    }

    hs[0][kh][j] = hidden[myb * Hn + j];
    const float bhj = bh[j];
    __syncthreads();

    float fin = 0.f;
    for (int t = 0; t < Ln; t++) {
        const int cur = t & 1;
        // prefetch token + x_proj early (latency hidden under the matvec)
        int tok  = is32 ? x32[myb * Ln + t] : (int)x64[myb * Ln + t];
        float xp = g_proj[tok * Hn + j];

        const ulonglong2* h0 = (const ulonglong2*)(&hs[cur][0][kh * 128]);
        const ulonglong2* h1 = (const ulonglong2*)(&hs[cur][1][kh * 128]);

        unsigned long long a00 = 0ull, a01 = 0ull, a10 = 0ull, a11 = 0ull;
        #pragma unroll
        for (int q = 0; q < 32; q++) {
            unsigned long long wp0 = wpair(wreg[2 * q]);       // (w[4q],   w[4q+1])
            unsigned long long wp1 = wpair(wreg[2 * q + 1]);   // (w[4q+2], w[4q+3])
            ulonglong2 p0 = h0[q];                             // batch0 h pairs (broadcast)
            ulonglong2 p1 = h1[q];                             // batch1
            ffma2(a00, wp0, p0.x); ffma2(a01, wp1, p0.y);
            ffma2(a10, wp0, p1.x); ffma2(a11, wp1, p1.y);
        }
        float2 s0 = unpack2(fadd2(a00, a01));   // batch0 partial (this k-half)
        float2 s1 = unpack2(fadd2(a10, a11));   // batch1 partial
        float p0 = s0.x + s0.y;
        float p1 = s1.x + s1.y;
        // combine k-halves across the thread pair
        p0 += __shfl_xor_sync(0xffffffffu, p0, 1);
        p1 += __shfl_xor_sync(0xffffffffu, p1, 1);
        float myp = kh ? p1 : p0;               // full dot for my batch
        float nh = tanh_fast(myp + xp + bhj);

        g_hout[((size_t)myb * Ln + t) * Hn + j] = nh;
        hs[cur ^ 1][kh][j] = nh;
        fin = nh;
        __syncthreads();
    }
    if (write_final) {
        dout[(size_t)Bn * Ln * Vn + myb * Hn + j] = fin;
    }
}

// ---------------- logits GEMM ----------------
// logits[r][v] = sum_k hout[r][k] * fcw[v][k] + fcb[v]
// Persistent grid; fcw^T resident in smem; 64-row tiles; 4x4 register blocking.
#define LOG_SMEM (65536 + 64 * 260 * 4)

__global__ void __launch_bounds__(256, 1) k_logits(const float* __restrict__ fcw,
        const float* __restrict__ fcb, float* __restrict__ out) {
    extern __shared__ char smem[];
    float* fT  = (float*)smem;              // [256][64]  fT[k][v] = fcw[v][k]
    float* hsm = (float*)(smem + 65536);    // [64][260]
    const int tid = threadIdx.x;
    const int tx = tid & 15, ty = tid >> 4;

    for (int p = tid; p < Vn * Hn; p += 256) {   // conflict-free transposed fill
        int v = p & 63, k = p >> 6;
        fT[k * 64 + v] = fcw[v * Hn + k];
    }
    float4 bias = *(const float4*)(fcb + 4 * tx);
    __syncthreads();

    const int ntiles = (Bn * Ln) / 64;      // 4096
    for (int tile = blockIdx.x; tile < ntiles; tile += gridDim.x) {
        const float4* src = (const float4*)(g_hout + (size_t)tile * 64 * Hn);
        for (int p = tid; p < 64 * 64; p += 256) {
            int row = p >> 6, kc = p & 63;
            *(float4*)(hsm + row * 260 + 4 * kc) = src[p];
        }
        __syncthreads();

        float acc[4][4];
        #pragma unroll
        for (int r = 0; r < 4; r++)
            #pragma unroll
            for (int c = 0; c < 4; c++) acc[r][c] = 0.f;

        #pragma unroll 8
        for (int k = 0; k < Hn; k++) {
            float4 b4 = *(const float4*)(fT + k * 64 + 4 * tx);
            float a0 = hsm[(4 * ty + 0) * 260 + k];
            float a1 = hsm[(4 * ty + 1) * 260 + k];
            float a2 = hsm[(4 * ty + 2) * 260 + k];
            float a3 = hsm[(4 * ty + 3) * 260 + k];
            acc[0][0] = fmaf(a0, b4.x, acc[0][0]); acc[0][1] = fmaf(a0, b4.y, acc[0][1]);
            acc[0][2] = fmaf(a0, b4.z, acc[0][2]); acc[0][3] = fmaf(a0, b4.w, acc[0][3]);
            acc[1][0] = fmaf(a1, b4.x, acc[1][0]); acc[1][1] = fmaf(a1, b4.y, acc[1][1]);
            acc[1][2] = fmaf(a1, b4.z, acc[1][2]); acc[1][3] = fmaf(a1, b4.w, acc[1][3]);
            acc[2][0] = fmaf(a2, b4.x, acc[2][0]); acc[2][1] = fmaf(a2, b4.y, acc[2][1]);
            acc[2][2] = fmaf(a2, b4.z, acc[2][2]); acc[2][3] = fmaf(a2, b4.w, acc[2][3]);
            acc[3][0] = fmaf(a3, b4.x, acc[3][0]); acc[3][1] = fmaf(a3, b4.y, acc[3][1]);
            acc[3][2] = fmaf(a3, b4.z, acc[3][2]); acc[3][3] = fmaf(a3, b4.w, acc[3][3]);
        }
        #pragma unroll
        for (int r = 0; r < 4; r++) {
            float4 o;
            o.x = acc[r][0] + bias.x; o.y = acc[r][1] + bias.y;
            o.z = acc[r][2] + bias.z; o.w = acc[r][3] + bias.w;
            *(float4*)(out + ((size_t)tile * 64 + 4 * ty + r) * 64 + 4 * tx) = o;
        }
        __syncthreads();
    }
}

// ---------------- launch ----------------
extern "C" void kernel_launch(void* const* d_in, const int* in_sizes, int n_in,
                              void* d_out, int out_size) {
    const void*  x      = d_in[0];
    const float* hidden = (const float*)d_in[1];
    const float* emb    = (const float*)d_in[2];
    const float* We     = (const float*)d_in[3];
    const float* be     = (const float*)d_in[4];
    const float* Wh     = (const float*)d_in[5];
    const float* bhp    = (const float*)d_in[6];
    const float* fcw    = (const float*)d_in[7];
    const float* fcb    = (const float*)d_in[8];
    float* out = (float*)d_out;

    cudaFuncSetAttribute(k_logits, cudaFuncAttributeMaxDynamicSharedMemorySize, LOG_SMEM);

    k_reset<<<1, 1>>>();
    k_detect<<<(Bn * Ln / 2 + 255) / 256, 256>>>((const unsigned int*)x);
    k_proj<<<Vn, Hn>>>(emb, We, be);

    int write_final = (out_size >= Bn * Ln * Vn + Bn * Hn) ? 1 : 0;
    k_rnn<<<Bn / 2, 512>>>(x, hidden, Wh, bhp, out, write_final);
    k_logits<<<148, 256, LOG_SMEM>>>(fcw, fcb, out);
}

// round 6
// speedup vs baseline: 1.0056x; 1.0005x over previous
#include <cuda_runtime.h>
#include <cuda_bf16.h>

#define Bn 256
#define Ln 1024
#define En 128
#define Hn 256
#define Vn 64

// ---- device-global scratch (no allocations allowed) ----
__device__ float g_proj[Vn * Hn];                    // token -> x_proj row (b_e folded in)
__device__ float g_hout[(size_t)Bn * Ln * Hn];       // all hidden states, 268MB
__device__ int   g_x_is32;

// ---------------- f32x2 helpers (Blackwell packed fp32) ----------------
__device__ __forceinline__ void ffma2(unsigned long long& acc,
                                      unsigned long long a, unsigned long long b) {
    asm("fma.rn.f32x2 %0, %1, %2, %0;" : "+l"(acc) : "l"(a), "l"(b));
}
__device__ __forceinline__ unsigned long long fadd2(unsigned long long a,
                                                    unsigned long long b) {
    unsigned long long r;
    asm("add.rn.f32x2 %0, %1, %2;" : "=l"(r) : "l"(a), "l"(b));
    return r;
}
__device__ __forceinline__ unsigned long long pack2u(unsigned int lo, unsigned int hi) {
    unsigned long long r;
    asm("mov.b64 %0, {%1, %2};" : "=l"(r) : "r"(lo), "r"(hi));
    return r;
}
__device__ __forceinline__ float2 unpack2(unsigned long long v) {
    unsigned int lo, hi;
    asm("mov.b64 {%0, %1}, %2;" : "=r"(lo), "=r"(hi) : "l"(v));
    return make_float2(__uint_as_float(lo), __uint_as_float(hi));
}
// expand bf16x2 reg (k0 lo | k1 hi) into f32x2 pair (k0, k1)
__device__ __forceinline__ unsigned long long wpair(unsigned int w) {
    return pack2u(w << 16, w & 0xffff0000u);
}
__device__ __forceinline__ float tanh_fast(float x) {
    float e = __expf(x + x);
    return 1.0f - __fdividef(2.0f, e + 1.0f);
}

// ---------------- dtype detection ----------------
__global__ void k_reset() { g_x_is32 = 0; }

__global__ void k_detect(const unsigned int* __restrict__ xw) {
    int i = blockIdx.x * blockDim.x + threadIdx.x;
    int idx = 2 * i + 1;                 // odd 32-bit words
    if (idx < Bn * Ln) {
        if (xw[idx] != 0u) g_x_is32 = 1; // int64 high halves are all zero (vals 0..63)
    }
}

// ---------------- projection table ----------------
// proj[v][h] = sum_e emb[v][e] * W_e[h][e] + b_e[h]
__global__ void k_proj(const float* __restrict__ emb, const float* __restrict__ We,
                       const float* __restrict__ be) {
    __shared__ float es[En];
    int v = blockIdx.x, j = threadIdx.x;
    if (j < En) es[j] = emb[v * En + j];
    __syncthreads();
    float acc = 0.f;
    #pragma unroll
    for (int e = 0; e < En; e++) acc = fmaf(es[e], We[j * En + e], acc);
    g_proj[v * Hn + j] = acc + be[j];
}

// ---------------- recurrence ----------------
// 128 CTAs x 512 threads. CTA owns batches (2c, 2c+1) for the full 1024-step chain.
// Split-k: thread pair (2j, 2j+1) shares output j; thread kh = tid&1 covers
// k in [kh*128, kh*128+128). Each thread's 128 W values live in 64 bf16x2
// REGISTERS (no smem W, no spill). Packed fma.rn.f32x2 throughout; cross-half
// reduction via one shfl_xor. After the reduction, thread kh owns batch kh
// for tanh + stores.
__global__ void __launch_bounds__(512, 1) k_rnn(const void* __restrict__ xraw,
        const float* __restrict__ hidden, const float* __restrict__ Wh,
        const float* __restrict__ bh, float* __restrict__ dout, int write_final) {
    __shared__ __align__(16) float hs[2][2][Hn];     // [buf][batch][256]
    const int tid = threadIdx.x;
    const int j  = tid >> 1;          // output index 0..255
    const int kh = tid & 1;           // k-half 0/1; also my batch after reduce
    const int b0 = 2 * blockIdx.x;
    const int myb = b0 + kh;
    const int is32 = g_x_is32;
    const int* x32       = (const int*)xraw;
    const long long* x64 = (const long long*)xraw;

    // load my half W_h row into registers (64 bf16x2 words)
    unsigned int wreg[64];
    const float4* Wh4 = (const float4*)Wh;
    #pragma unroll
    for (int q = 0; q < 32; q++) {
        float4 w4 = Wh4[j * 64 + kh * 32 + q];
        __nv_bfloat162 lo2 = __floats2bfloat162_rn(w4.x, w4.y);
        __nv_bfloat162 hi2 = __floats2bfloat162_rn(w4.z, w4.w);
        wreg[2 * q]     = *(unsigned int*)&lo2;
        wreg[2 * q + 1] = *(unsigned int*)&hi2;
    }

    hs[0][kh][j] = hidden[myb * Hn + j];
    const float bhj = bh[j];
    __syncthreads();

    float fin = 0.f;
    for (int t = 0; t < Ln; t++) {
        const int cur = t & 1;
        // prefetch token + x_proj early (latency hidden under the matvec)
        int tok  = is32 ? x32[myb * Ln + t] : (int)x64[myb * Ln + t];
        float xp = g_proj[tok * Hn + j];

        const ulonglong2* h0 = (const ulonglong2*)(&hs[cur][0][kh * 128]);
        const ulonglong2* h1 = (const ulonglong2*)(&hs[cur][1][kh * 128]);

        unsigned long long a00 = 0ull, a01 = 0ull, a10 = 0ull, a11 = 0ull;
        #pragma unroll
        for (int q = 0; q < 32; q++) {
            unsigned long long wp0 = wpair(wreg[2 * q]);       // (w[4q],   w[4q+1])
            unsigned long long wp1 = wpair(wreg[2 * q + 1]);   // (w[4q+2], w[4q+3])
            ulonglong2 p0 = h0[q];                             // batch0 h pairs (broadcast)
            ulonglong2 p1 = h1[q];                             // batch1
            ffma2(a00, wp0, p0.x); ffma2(a01, wp1, p0.y);
            ffma2(a10, wp0, p1.x); ffma2(a11, wp1, p1.y);
        }
        float2 s0 = unpack2(fadd2(a00, a01));   // batch0 partial (this k-half)
        float2 s1 = unpack2(fadd2(a10, a11));   // batch1 partial
        float p0 = s0.x + s0.y;
        float p1 = s1.x + s1.y;
        // combine k-halves across the thread pair
        p0 += __shfl_xor_sync(0xffffffffu, p0, 1);
        p1 += __shfl_xor_sync(0xffffffffu, p1, 1);
        float myp = kh ? p1 : p0;               // full dot for my batch
        float nh = tanh_fast(myp + xp + bhj);

        g_hout[((size_t)myb * Ln + t) * Hn + j] = nh;
        hs[cur ^ 1][kh][j] = nh;
        fin = nh;
        __syncthreads();
    }
    if (write_final) {
        dout[(size_t)Bn * Ln * Vn + myb * Hn + j] = fin;
    }
}

// ---------------- logits GEMM ----------------
// logits[r][v] = sum_k hout[r][k] * fcw[v][k] + fcb[v]
// Persistent grid; fcw^T resident in smem; 64-row tiles; 4x4 register blocking.
#define LOG_SMEM (65536 + 64 * 260 * 4)

__global__ void __launch_bounds__(256, 1) k_logits(const float* __restrict__ fcw,
        const float* __restrict__ fcb, float* __restrict__ out) {
    extern __shared__ char smem[];
    float* fT  = (float*)smem;              // [256][64]  fT[k][v] = fcw[v][k]
    float* hsm = (float*)(smem + 65536);    // [64][260]
    const int tid = threadIdx.x;
    const int tx = tid & 15, ty = tid >> 4;

    for (int p = tid; p < Vn * Hn; p += 256) {   // conflict-free transposed fill
        int v = p & 63, k = p >> 6;
        fT[k * 64 + v] = fcw[v * Hn + k];
    }
    float4 bias = *(const float4*)(fcb + 4 * tx);
    __syncthreads();

    const int ntiles = (Bn * Ln) / 64;      // 4096
    for (int tile = blockIdx.x; tile < ntiles; tile += gridDim.x) {
        const float4* src = (const float4*)(g_hout + (size_t)tile * 64 * Hn);
        for (int p = tid; p < 64 * 64; p += 256) {
            int row = p >> 6, kc = p & 63;
            *(float4*)(hsm + row * 260 + 4 * kc) = src[p];
        }
        __syncthreads();

        float acc[4][4];
        #pragma unroll
        for (int r = 0; r < 4; r++)
            #pragma unroll
            for (int c = 0; c < 4; c++) acc[r][c] = 0.f;

        #pragma unroll 8
        for (int k = 0; k < Hn; k++) {
            float4 b4 = *(const float4*)(fT + k * 64 + 4 * tx);
            float a0 = hsm[(4 * ty + 0) * 260 + k];
            float a1 = hsm[(4 * ty + 1) * 260 + k];
            float a2 = hsm[(4 * ty + 2) * 260 + k];
            float a3 = hsm[(4 * ty + 3) * 260 + k];
            acc[0][0] = fmaf(a0, b4.x, acc[0][0]); acc[0][1] = fmaf(a0, b4.y, acc[0][1]);
            acc[0][2] = fmaf(a0, b4.z, acc[0][2]); acc[0][3] = fmaf(a0, b4.w, acc[0][3]);
            acc[1][0] = fmaf(a1, b4.x, acc[1][0]); acc[1][1] = fmaf(a1, b4.y, acc[1][1]);
            acc[1][2] = fmaf(a1, b4.z, acc[1][2]); acc[1][3] = fmaf(a1, b4.w, acc[1][3]);
            acc[2][0] = fmaf(a2, b4.x, acc[2][0]); acc[2][1] = fmaf(a2, b4.y, acc[2][1]);
            acc[2][2] = fmaf(a2, b4.z, acc[2][2]); acc[2][3] = fmaf(a2, b4.w, acc[2][3]);
            acc[3][0] = fmaf(a3, b4.x, acc[3][0]); acc[3][1] = fmaf(a3, b4.y, acc[3][1]);
            acc[3][2] = fmaf(a3, b4.z, acc[3][2]); acc[3][3] = fmaf(a3, b4.w, acc[3][3]);
        }
        #pragma unroll
        for (int r = 0; r < 4; r++) {
            float4 o;
            o.x = acc[r][0] + bias.x; o.y = acc[r][1] + bias.y;
            o.z = acc[r][2] + bias.z; o.w = acc[r][3] + bias.w;
            *(float4*)(out + ((size_t)tile * 64 + 4 * ty + r) * 64 + 4 * tx) = o;
        }
        __syncthreads();
    }
}

// ---------------- launch ----------------
extern "C" void kernel_launch(void* const* d_in, const int* in_sizes, int n_in,
                              void* d_out, int out_size) {
    const void*  x      = d_in[0];
    const float* hidden = (const float*)d_in[1];
    const float* emb    = (const float*)d_in[2];
    const float* We     = (const float*)d_in[3];
    const float* be     = (const float*)d_in[4];
    const float* Wh     = (const float*)d_in[5];
    const float* bhp    = (const float*)d_in[6];
    const float* fcw    = (const float*)d_in[7];
    const float* fcb    = (const float*)d_in[8];
    float* out = (float*)d_out;

    cudaFuncSetAttribute(k_logits, cudaFuncAttributeMaxDynamicSharedMemorySize, LOG_SMEM);

    k_reset<<<1, 1>>>();
    k_detect<<<(Bn * Ln / 2 + 255) / 256, 256>>>((const unsigned int*)x);
    k_proj<<<Vn, Hn>>>(emb, We, be);

    int write_final = (out_size >= Bn * Ln * Vn + Bn * Hn) ? 1 : 0;
    k_rnn<<<Bn / 2, 512>>>(x, hidden, Wh, bhp, out, write_final);
    k_logits<<<148, 256, LOG_SMEM>>>(fcw, fcb, out);
}

// round 7
// speedup vs baseline: 1.4531x; 1.4451x over previous
#include <cuda_runtime.h>
#include <cuda_bf16.h>

#define Bn 256
#define Ln 1024
#define En 128
#define Hn 256
#define Vn 64

// ---- device-global scratch (no allocations allowed) ----
__device__ float g_proj[Vn * Hn];                    // token -> x_proj row (b_e folded in)
__device__ float g_hout[(size_t)Bn * Ln * Hn];       // all hidden states, 268MB
__device__ int   g_x_is32;

// ---------------- f32x2 helpers (Blackwell packed fp32) ----------------
__device__ __forceinline__ void ffma2(unsigned long long& acc,
                                      unsigned long long a, unsigned long long b) {
    asm("fma.rn.f32x2 %0, %1, %2, %0;" : "+l"(acc) : "l"(a), "l"(b));
}
__device__ __forceinline__ unsigned long long fadd2(unsigned long long a,
                                                    unsigned long long b) {
    unsigned long long r;
    asm("add.rn.f32x2 %0, %1, %2;" : "=l"(r) : "l"(a), "l"(b));
    return r;
}
__device__ __forceinline__ unsigned long long pack2u(unsigned int lo, unsigned int hi) {
    unsigned long long r;
    asm("mov.b64 %0, {%1, %2};" : "=l"(r) : "r"(lo), "r"(hi));
    return r;
}
__device__ __forceinline__ float2 unpack2(unsigned long long v) {
    unsigned int lo, hi;
    asm("mov.b64 {%0, %1}, %2;" : "=r"(lo), "=r"(hi) : "l"(v));
    return make_float2(__uint_as_float(lo), __uint_as_float(hi));
}
// expand bf16x2 reg (k0 lo | k1 hi) into f32x2 pair (k0, k1)
__device__ __forceinline__ unsigned long long wpair(unsigned int w) {
    return pack2u(w << 16, w & 0xffff0000u);
}
__device__ __forceinline__ float tanh_fast(float x) {
    float e = __expf(x + x);
    return 1.0f - __fdividef(2.0f, e + 1.0f);
}

// ---------------- dtype detection ----------------
__global__ void k_reset() { g_x_is32 = 0; }

__global__ void k_detect(const unsigned int* __restrict__ xw) {
    int i = blockIdx.x * blockDim.x + threadIdx.x;
    int idx = 2 * i + 1;                 // odd 32-bit words
    if (idx < Bn * Ln) {
        if (xw[idx] != 0u) g_x_is32 = 1; // int64 high halves are all zero (vals 0..63)
    }
}

// ---------------- projection table ----------------
// proj[v][h] = sum_e emb[v][e] * W_e[h][e] + b_e[h]
__global__ void k_proj(const float* __restrict__ emb, const float* __restrict__ We,
                       const float* __restrict__ be) {
    __shared__ float es[En];
    int v = blockIdx.x, j = threadIdx.x;
    if (j < En) es[j] = emb[v * En + j];
    __syncthreads();
    float acc = 0.f;
    #pragma unroll
    for (int e = 0; e < En; e++) acc = fmaf(es[e], We[j * En + e], acc);
    g_proj[v * Hn + j] = acc + be[j];
}

// ---------------- recurrence ----------------
// 128 CTAs x 512 threads. CTA owns batches (2c, 2c+1) for the full chain.
// W_h stays in SMEM as bf16x2 (no register residency -> no spill).
// Split-k: thread pair (2j, 2j+1) shares output j; kh = tid&1 covers
// k in [kh*128, kh*128+128). Each thread accumulates partials for BOTH
// batches with packed fma.rn.f32x2; ONE shfl_xor swaps cross-half partials
// (thread kh keeps batch kh). h k-halves are padded 132 floats apart so
// even/odd-lane broadcasts hit disjoint banks (1 phase, not 2).
//
// smem: Ws uint2[64][256] = 128KB, index (2*i+kh)*256 + j
//       hs float[2 buf][2 batch][264], half kh at offset kh*132
#define HS_HALF 132
#define HS_BATCH 264
#define HS_BUF 528
#define RNN_SMEM (131072 + 2 * HS_BUF * 4)

__global__ void __launch_bounds__(512, 1) k_rnn(const void* __restrict__ xraw,
        const float* __restrict__ hidden, const float* __restrict__ Wh,
        const float* __restrict__ bh, float* __restrict__ dout, int write_final) {
    extern __shared__ __align__(16) char smem[];
    uint2* Ws  = (uint2*)smem;                    // 128KB
    float* hsf = (float*)(smem + 131072);         // 2*528 floats
    const int tid = threadIdx.x;
    const int j  = tid >> 1;          // output index 0..255
    const int kh = tid & 1;           // k-half 0/1; also my batch after reduce
    const int b0 = 2 * blockIdx.x;
    const int myb = b0 + kh;
    const int is32 = g_x_is32;
    const int* x32       = (const int*)xraw;
    const long long* x64 = (const long long*)xraw;

    // pack W_h -> bf16x2 smem: Ws[(2*i+kh)*256 + jj] = W[jj][kh*128+4i .. +3]
    const float4* Wh4 = (const float4*)Wh;
    for (int p = tid; p < 64 * 256; p += 512) {
        int jj = p & 255, r = p >> 8;           // r = 2*i + khw
        int i = r >> 1, khw = r & 1;
        float4 w4 = Wh4[jj * 64 + khw * 32 + i];
        __nv_bfloat162 lo2 = __floats2bfloat162_rn(w4.x, w4.y);
        __nv_bfloat162 hi2 = __floats2bfloat162_rn(w4.z, w4.w);
        uint2 u;
        u.x = *(unsigned int*)&lo2;
        u.y = *(unsigned int*)&hi2;
        Ws[r * 256 + jj] = u;
    }
    // init h: thread (j,kh) seeds batch kh element j
    {
        int pos = (j >> 7) * HS_HALF + (j & 127);
        hsf[kh * HS_BATCH + pos] = hidden[myb * Hn + j];
    }
    const float bhj = bh[j];
    __syncthreads();

    const uint2* Wsk = Ws + kh * 256 + j;   // stride 512 uint2 per i

    float fin = 0.f;
    for (int t = 0; t < Ln; t++) {
        const int cur = t & 1;
        // prefetch token + x_proj early (latency hidden under the matvec)
        int tok  = is32 ? x32[myb * Ln + t] : (int)x64[myb * Ln + t];
        float xp = g_proj[tok * Hn + j];

        const ulonglong2* h0 = (const ulonglong2*)(hsf + cur * HS_BUF + kh * HS_HALF);
        const ulonglong2* h1 = (const ulonglong2*)(hsf + cur * HS_BUF + HS_BATCH + kh * HS_HALF);

        unsigned long long a00 = 0ull, a01 = 0ull, a10 = 0ull, a11 = 0ull;
        #pragma unroll
        for (int i = 0; i < 32; i++) {
            uint2 w = Wsk[i * 512];
            unsigned long long wp0 = wpair(w.x);   // (w[4i],   w[4i+1])
            unsigned long long wp1 = wpair(w.y);   // (w[4i+2], w[4i+3])
            ulonglong2 p0 = h0[i];                 // batch0 h pairs (16-lane broadcast)
            ulonglong2 p1 = h1[i];                 // batch1
            ffma2(a00, wp0, p0.x); ffma2(a01, wp1, p0.y);
            ffma2(a10, wp0, p1.x); ffma2(a11, wp1, p1.y);
        }
        float2 s0 = unpack2(fadd2(a00, a01));   // batch0 partial (this k-half)
        float2 s1 = unpack2(fadd2(a10, a11));   // batch1 partial
        float pb0 = s0.x + s0.y;
        float pb1 = s1.x + s1.y;
        // single shfl: ship the OTHER batch's partial to my pair thread
        float send = kh ? pb0 : pb1;
        float recv = __shfl_xor_sync(0xffffffffu, send, 1);
        float myp  = (kh ? pb1 : pb0) + recv;   // full dot for my batch
        float nh = tanh_fast(myp + xp + bhj);

        g_hout[((size_t)myb * Ln + t) * Hn + j] = nh;
        int pos = (j >> 7) * HS_HALF + (j & 127);
        hsf[(cur ^ 1) * HS_BUF + kh * HS_BATCH + pos] = nh;
        fin = nh;
        __syncthreads();
    }
    if (write_final) {
        dout[(size_t)Bn * Ln * Vn + myb * Hn + j] = fin;
    }
}

// ---------------- logits GEMM ----------------
// logits[r][v] = sum_k hout[r][k] * fcw[v][k] + fcb[v]
// Persistent grid; fcw^T resident in smem; 64-row tiles; 4x4 register blocking.
#define LOG_SMEM (65536 + 64 * 260 * 4)

__global__ void __launch_bounds__(256, 1) k_logits(const float* __restrict__ fcw,
        const float* __restrict__ fcb, float* __restrict__ out) {
    extern __shared__ char smem[];
    float* fT  = (float*)smem;              // [256][64]  fT[k][v] = fcw[v][k]
    float* hsm = (float*)(smem + 65536);    // [64][260]
    const int tid = threadIdx.x;
    const int tx = tid & 15, ty = tid >> 4;

    for (int p = tid; p < Vn * Hn; p += 256) {   // conflict-free transposed fill
        int v = p & 63, k = p >> 6;
        fT[k * 64 + v] = fcw[v * Hn + k];
    }
    float4 bias = *(const float4*)(fcb + 4 * tx);
    __syncthreads();

    const int ntiles = (Bn * Ln) / 64;      // 4096
    for (int tile = blockIdx.x; tile < ntiles; tile += gridDim.x) {
        const float4* src = (const float4*)(g_hout + (size_t)tile * 64 * Hn);
        for (int p = tid; p < 64 * 64; p += 256) {
            int row = p >> 6, kc = p & 63;
            *(float4*)(hsm + row * 260 + 4 * kc) = src[p];
        }
        __syncthreads();

        float acc[4][4];
        #pragma unroll
        for (int r = 0; r < 4; r++)
            #pragma unroll
            for (int c = 0; c < 4; c++) acc[r][c] = 0.f;

        #pragma unroll 8
        for (int k = 0; k < Hn; k++) {
            float4 b4 = *(const float4*)(fT + k * 64 + 4 * tx);
            float a0 = hsm[(4 * ty + 0) * 260 + k];
            float a1 = hsm[(4 * ty + 1) * 260 + k];
            float a2 = hsm[(4 * ty + 2) * 260 + k];
            float a3 = hsm[(4 * ty + 3) * 260 + k];
            acc[0][0] = fmaf(a0, b4.x, acc[0][0]); acc[0][1] = fmaf(a0, b4.y, acc[0][1]);
            acc[0][2] = fmaf(a0, b4.z, acc[0][2]); acc[0][3] = fmaf(a0, b4.w, acc[0][3]);
            acc[1][0] = fmaf(a1, b4.x, acc[1][0]); acc[1][1] = fmaf(a1, b4.y, acc[1][1]);
            acc[1][2] = fmaf(a1, b4.z, acc[1][2]); acc[1][3] = fmaf(a1, b4.w, acc[1][3]);
            acc[2][0] = fmaf(a2, b4.x, acc[2][0]); acc[2][1] = fmaf(a2, b4.y, acc[2][1]);
            acc[2][2] = fmaf(a2, b4.z, acc[2][2]); acc[2][3] = fmaf(a2, b4.w, acc[2][3]);
            acc[3][0] = fmaf(a3, b4.x, acc[3][0]); acc[3][1] = fmaf(a3, b4.y, acc[3][1]);
            acc[3][2] = fmaf(a3, b4.z, acc[3][2]); acc[3][3] = fmaf(a3, b4.w, acc[3][3]);
        }
        #pragma unroll
        for (int r = 0; r < 4; r++) {
            float4 o;
            o.x = acc[r][0] + bias.x; o.y = acc[r][1] + bias.y;
            o.z = acc[r][2] + bias.z; o.w = acc[r][3] + bias.w;
            *(float4*)(out + ((size_t)tile * 64 + 4 * ty + r) * 64 + 4 * tx) = o;
        }
        __syncthreads();
    }
}

// ---------------- launch ----------------
extern "C" void kernel_launch(void* const* d_in, const int* in_sizes, int n_in,
                              void* d_out, int out_size) {
    const void*  x      = d_in[0];
    const float* hidden = (const float*)d_in[1];
    const float* emb    = (const float*)d_in[2];
    const float* We     = (const float*)d_in[3];
    const float* be     = (const float*)d_in[4];
    const float* Wh     = (const float*)d_in[5];
    const float* bhp    = (const float*)d_in[6];
    const float* fcw    = (const float*)d_in[7];
    const float* fcb    = (const float*)d_in[8];
    float* out = (float*)d_out;

    cudaFuncSetAttribute(k_rnn,    cudaFuncAttributeMaxDynamicSharedMemorySize, RNN_SMEM);
    cudaFuncSetAttribute(k_logits, cudaFuncAttributeMaxDynamicSharedMemorySize, LOG_SMEM);

    k_reset<<<1, 1>>>();
    k_detect<<<(Bn * Ln / 2 + 255) / 256, 256>>>((const unsigned int*)x);
    k_proj<<<Vn, Hn>>>(emb, We, be);

    int write_final = (out_size >= Bn * Ln * Vn + Bn * Hn) ? 1 : 0;
    k_rnn<<<Bn / 2, 512, RNN_SMEM>>>(x, hidden, Wh, bhp, out, write_final);
    k_logits<<<148, 256, LOG_SMEM>>>(fcw, fcb, out);
}

// round 9
// speedup vs baseline: 1.8667x; 1.2846x over previous
#include <cuda_runtime.h>
#include <cuda_bf16.h>

#define Bn 256
#define Ln 1024
#define En 128
#define Hn 256
#define Vn 64

// ---- device-global scratch (no allocations allowed) ----
__device__ float g_proj[Vn * Hn];                    // token -> x_proj row (b_e folded in)
__device__ float g_hout[(size_t)Bn * Ln * Hn];       // all hidden states, 268MB
__device__ int   g_x_is32;

// ---------------- f32x2 helpers (Blackwell packed fp32) ----------------
__device__ __forceinline__ void ffma2(unsigned long long& acc,
                                      unsigned long long a, unsigned long long b) {
    asm("fma.rn.f32x2 %0, %1, %2, %0;" : "+l"(acc) : "l"(a), "l"(b));
}
__device__ __forceinline__ unsigned long long fadd2(unsigned long long a,
                                                    unsigned long long b) {
    unsigned long long r;
    asm("add.rn.f32x2 %0, %1, %2;" : "=l"(r) : "l"(a), "l"(b));
    return r;
}
__device__ __forceinline__ unsigned long long pack2u(unsigned int lo, unsigned int hi) {
    unsigned long long r;
    asm("mov.b64 %0, {%1, %2};" : "=l"(r) : "r"(lo), "r"(hi));
    return r;
}
__device__ __forceinline__ unsigned long long dup2f(float a) {
    unsigned int u = __float_as_uint(a);
    return pack2u(u, u);
}
__device__ __forceinline__ float2 unpack2(unsigned long long v) {
    unsigned int lo, hi;
    asm("mov.b64 {%0, %1}, %2;" : "=r"(lo), "=r"(hi) : "l"(v));
    return make_float2(__uint_as_float(lo), __uint_as_float(hi));
}
// expand bf16x2 reg (k0 lo | k1 hi) into f32x2 pair (k0, k1)
__device__ __forceinline__ unsigned long long wpair(unsigned int w) {
    return pack2u(w << 16, w & 0xffff0000u);
}
__device__ __forceinline__ float tanh_fast(float x) {
    float e = __expf(x + x);
    return 1.0f - __fdividef(2.0f, e + 1.0f);
}

// ---------------- dtype detection ----------------
__global__ void k_reset() { g_x_is32 = 0; }

__global__ void k_detect(const unsigned int* __restrict__ xw) {
    int i = blockIdx.x * blockDim.x + threadIdx.x;
    int idx = 2 * i + 1;                 // odd 32-bit words
    if (idx < Bn * Ln) {
        if (xw[idx] != 0u) g_x_is32 = 1; // int64 high halves are all zero (vals 0..63)
    }
}

// ---------------- projection table ----------------
// proj[v][h] = sum_e emb[v][e] * W_e[h][e] + b_e[h]
__global__ void k_proj(const float* __restrict__ emb, const float* __restrict__ We,
                       const float* __restrict__ be) {
    __shared__ float es[En];
    int v = blockIdx.x, j = threadIdx.x;
    if (j < En) es[j] = emb[v * En + j];
    __syncthreads();
    float acc = 0.f;
    #pragma unroll
    for (int e = 0; e < En; e++) acc = fmaf(es[e], We[j * En + e], acc);
    g_proj[v * Hn + j] = acc + be[j];
}

// ---------------- recurrence ----------------
// Round-2 structure (proven fastest) + packed fma.rn.f32x2 inner loop.
// 128 CTAs x 256 threads; CTA owns batches (2c, 2c+1) end-to-end.
// W_h in smem as bf16x2 (Wp[q][j] = W[j][4q..4q+3]); h double-buffered in smem.
// Per iter: 1 LDS.64 (W) + 2 LDS.128 (h, warp-broadcast) + 4 FFMA2 -> 8 MACs.
#define RNN_SMEM (131072 + 4096)

__global__ void __launch_bounds__(256, 1) k_rnn(const void* __restrict__ xraw,
        const float* __restrict__ hidden, const float* __restrict__ Wh,
        const float* __restrict__ bh, float* __restrict__ dout, int write_final) {
    extern __shared__ __align__(16) char smem[];
    uint2* Wp = (uint2*)smem;                 // [64][256] uint2 = 128KB
    float* hs = (float*)(smem + 131072);      // [2 buf][2 batch][256]
    const int j  = threadIdx.x;
    const int b0 = 2 * blockIdx.x, b1 = b0 + 1;
    const int is32 = g_x_is32;
    const int* x32       = (const int*)xraw;
    const long long* x64 = (const long long*)xraw;

    // pack W_h -> bf16 smem, conflict-free stores
    for (int p = j; p < 64 * 256; p += 256) {
        int jj = p & 255, q = p >> 8;
        const float4 w4 = *(const float4*)(Wh + jj * Hn + 4 * q);
        __nv_bfloat162 lo2 = __floats2bfloat162_rn(w4.x, w4.y);
        __nv_bfloat162 hi2 = __floats2bfloat162_rn(w4.z, w4.w);
        uint2 u;
        u.x = *(unsigned int*)&lo2;
        u.y = *(unsigned int*)&hi2;
        Wp[q * 256 + jj] = u;
    }
    hs[j]       = hidden[b0 * Hn + j];
    hs[256 + j] = hidden[b1 * Hn + j];
    const float bhj = bh[j];
    __syncthreads();

    float fin0 = 0.f, fin1 = 0.f;
    for (int t = 0; t < Ln; t++) {
        const int cur = t & 1;
        // prefetch token + x_proj early (long latency hidden under the matvec)
        int tok0 = is32 ? x32[b0 * Ln + t] : (int)x64[b0 * Ln + t];
        int tok1 = is32 ? x32[b1 * Ln + t] : (int)x64[b1 * Ln + t];
        float xp0 = g_proj[tok0 * Hn + j];
        float xp1 = g_proj[tok1 * Hn + j];

        const ulonglong2* h0 = (const ulonglong2*)(hs + cur * 512);
        const ulonglong2* h1 = (const ulonglong2*)(hs + cur * 512 + 256);

        unsigned long long a00 = 0ull, a01 = 0ull, a10 = 0ull, a11 = 0ull;
        #pragma unroll
        for (int q = 0; q < 64; q++) {
            uint2 w = Wp[q * 256 + j];             // my row chunk (conflict-free LDS.64)
            unsigned long long wp0 = wpair(w.x);   // (w[4q],   w[4q+1])
            unsigned long long wp1 = wpair(w.y);   // (w[4q+2], w[4q+3])
            ulonglong2 p0 = h0[q];                 // batch0 h pairs (broadcast)
            ulonglong2 p1 = h1[q];                 // batch1
            ffma2(a00, wp0, p0.x); ffma2(a01, wp1, p0.y);
            ffma2(a10, wp0, p1.x); ffma2(a11, wp1, p1.y);
        }
        float2 s0 = unpack2(fadd2(a00, a01));
        float2 s1 = unpack2(fadd2(a10, a11));
        float nh0 = tanh_fast(s0.x + s0.y + xp0 + bhj);
        float nh1 = tanh_fast(s1.x + s1.y + xp1 + bhj);

        g_hout[((size_t)b0 * Ln + t) * Hn + j] = nh0;
        g_hout[((size_t)b1 * Ln + t) * Hn + j] = nh1;
        const int nxt = cur ^ 1;
        hs[nxt * 512 + j]       = nh0;
        hs[nxt * 512 + 256 + j] = nh1;
        fin0 = nh0; fin1 = nh1;
        __syncthreads();
    }
    if (write_final) {
        dout[(size_t)Bn * Ln * Vn + b0 * Hn + j] = fin0;
        dout[(size_t)Bn * Ln * Vn + b1 * Hn + j] = fin1;
    }
}

// ---------------- logits GEMM ----------------
// logits[r][v] = sum_k hout[r][k] * fcw[v][k] + fcb[v]
// Round-2 tile structure (row-major hsm fill, conflict-free) with packed
// f32x2 FMAs along the V dimension: fT row pairs load directly as ulonglong2;
// h scalar is duplicated. FMA-pipe work per k halves (8 FFMA2 vs 16 FFMA).
#define LOG_SMEM (65536 + 64 * 260 * 4)

__global__ void __launch_bounds__(256, 1) k_logits(const float* __restrict__ fcw,
        const float* __restrict__ fcb, float* __restrict__ out) {
    extern __shared__ char smem[];
    float* fT  = (float*)smem;              // [256][64]  fT[k][v] = fcw[v][k]
    float* hsm = (float*)(smem + 65536);    // [64][260]
    const int tid = threadIdx.x;
    const int tx = tid & 15, ty = tid >> 4;

    for (int p = tid; p < Vn * Hn; p += 256) {   // conflict-free transposed fill
        int v = p & 63, k = p >> 6;
        fT[k * 64 + v] = fcw[v * Hn + k];
    }
    float4 bias = *(const float4*)(fcb + 4 * tx);
    __syncthreads();

    const int ntiles = (Bn * Ln) / 64;      // 4096
    for (int tile = blockIdx.x; tile < ntiles; tile += gridDim.x) {
        const float4* src = (const float4*)(g_hout + (size_t)tile * 64 * Hn);
        for (int p = tid; p < 64 * 64; p += 256) {
            int row = p >> 6, kc = p & 63;
            *(float4*)(hsm + row * 260 + 4 * kc) = src[p];
        }
        __syncthreads();

        // acc[r][cp]: row r (of 4), column pair cp (v = 4tx + 2cp + {0,1})
        unsigned long long acc[4][2];
        #pragma unroll
        for (int r = 0; r < 4; r++) { acc[r][0] = 0ull; acc[r][1] = 0ull; }

        #pragma unroll 8
        for (int k = 0; k < Hn; k++) {
            ulonglong2 bp = *(const ulonglong2*)(fT + k * 64 + 4 * tx); // (v0,v1),(v2,v3)
            unsigned long long a0 = dup2f(hsm[(4 * ty + 0) * 260 + k]);
            unsigned long long a1 = dup2f(hsm[(4 * ty + 1) * 260 + k]);
            unsigned long long a2 = dup2f(hsm[(4 * ty + 2) * 260 + k]);
            unsigned long long a3 = dup2f(hsm[(4 * ty + 3) * 260 + k]);
            ffma2(acc[0][0], a0, bp.x); ffma2(acc[0][1], a0, bp.y);
            ffma2(acc[1][0], a1, bp.x); ffma2(acc[1][1], a1, bp.y);
            ffma2(acc[2][0], a2, bp.x); ffma2(acc[2][1], a2, bp.y);
            ffma2(acc[3][0], a3, bp.x); ffma2(acc[3][1], a3, bp.y);
        }
        #pragma unroll
        for (int r = 0; r < 4; r++) {
            float2 c01 = unpack2(acc[r][0]);
            float2 c23 = unpack2(acc[r][1]);
            float4 o;
            o.x = c01.x + bias.x; o.y = c01.y + bias.y;
            o.z = c23.x + bias.z; o.w = c23.y + bias.w;
            *(float4*)(out + ((size_t)tile * 64 + 4 * ty + r) * 64 + 4 * tx) = o;
        }
        __syncthreads();
    }
}

// ---------------- launch ----------------
extern "C" void kernel_launch(void* const* d_in, const int* in_sizes, int n_in,
                              void* d_out, int out_size) {
    const void*  x      = d_in[0];
    const float* hidden = (const float*)d_in[1];
    const float* emb    = (const float*)d_in[2];
    const float* We     = (const float*)d_in[3];
    const float* be     = (const float*)d_in[4];
    const float* Wh     = (const float*)d_in[5];
    const float* bhp    = (const float*)d_in[6];
    const float* fcw    = (const float*)d_in[7];
    const float* fcb    = (const float*)d_in[8];
    float* out = (float*)d_out;

    cudaFuncSetAttribute(k_rnn,    cudaFuncAttributeMaxDynamicSharedMemorySize, RNN_SMEM);
    cudaFuncSetAttribute(k_logits, cudaFuncAttributeMaxDynamicSharedMemorySize, LOG_SMEM);

    k_reset<<<1, 1>>>();
    k_detect<<<(Bn * Ln / 2 + 255) / 256, 256>>>((const unsigned int*)x);
    k_proj<<<Vn, Hn>>>(emb, We, be);

    int write_final = (out_size >= Bn * Ln * Vn + Bn * Hn) ? 1 : 0;
    k_rnn<<<Bn / 2, Hn, RNN_SMEM>>>(x, hidden, Wh, bhp, out, write_final);
    k_logits<<<148, 256, LOG_SMEM>>>(fcw, fcb, out);
}

// round 12
// speedup vs baseline: 3.3697x; 1.8052x over previous
#include <cuda_runtime.h>
#include <cuda_bf16.h>
#include <cstdint>

#define Bn 256
#define Ln 1024
#define En 128
#define Hn 256
#define Vn 64
#define NB 8                  // batches per CTA (MMA N)
#define NCTA (Bn / NB)        // 32 CTAs

// ---- device-global scratch (no allocations allowed) ----
__device__ float g_proj[Vn * Hn];                    // token -> x_proj row (b_e folded in)
__device__ float g_hout[(size_t)Bn * Ln * Hn];       // all hidden states, 268MB
__device__ int   g_x_is32;

__device__ __forceinline__ float tanh_fast(float x) {
    float e = __expf(x + x);
    return 1.0f - __fdividef(2.0f, e + 1.0f);
}

// ---------------- f32x2 helpers (for k_logits) ----------------
__device__ __forceinline__ void ffma2(unsigned long long& acc,
                                      unsigned long long a, unsigned long long b) {
    asm("fma.rn.f32x2 %0, %1, %2, %0;" : "+l"(acc) : "l"(a), "l"(b));
}
__device__ __forceinline__ unsigned long long dup2f(float a) {
    unsigned int u = __float_as_uint(a);
    unsigned long long r;
    asm("mov.b64 %0, {%1, %2};" : "=l"(r) : "r"(u), "r"(u));
    return r;
}
__device__ __forceinline__ float2 unpack2(unsigned long long v) {
    unsigned int lo, hi;
    asm("mov.b64 {%0, %1}, %2;" : "=r"(lo), "=r"(hi) : "l"(v));
    return make_float2(__uint_as_float(lo), __uint_as_float(hi));
}

// ---------------- dtype detection ----------------
__global__ void k_reset() { g_x_is32 = 0; }

__global__ void k_detect(const unsigned int* __restrict__ xw) {
    int i = blockIdx.x * blockDim.x + threadIdx.x;
    int idx = 2 * i + 1;
    if (idx < Bn * Ln) {
        if (xw[idx] != 0u) g_x_is32 = 1;   // int64 high halves all zero (vals 0..63)
    }
}

// ---------------- projection table ----------------
__global__ void k_proj(const float* __restrict__ emb, const float* __restrict__ We,
                       const float* __restrict__ be) {
    __shared__ float es[En];
    int v = blockIdx.x, j = threadIdx.x;
    if (j < En) es[j] = emb[v * En + j];
    __syncthreads();
    float acc = 0.f;
    #pragma unroll
    for (int e = 0; e < En; e++) acc = fmaf(es[e], We[j * En + e], acc);
    g_proj[v * Hn + j] = acc + be[j];
}

// ---------------- recurrence on HMMA (mma.sync m16n8k16 bf16) ----------------
// 32 CTAs x 512 threads (16 warps). CTA owns batches [8c, 8c+8) end-to-end.
// Warp w owns output rows [16w, 16w+16): one m16 tile x 16 K-steps.
// W_h lives in REGISTERS as A fragments (64 x b32/thread). h is the B operand,
// kept in smem in EXACT B-fragment layout (double-buffered, 4KB each):
//   byte addr(j, n) = (j>>4)*256 + (((n<<2)|((j&7)>>1))<<3)
//                   + (((j>>3)&1)<<2) + ((j&1)<<1)
// Reader: per k-step kk, thread reads LDS.64 at kk*256 + lane*8 -> {b0, b1}.
// Epilogue: acc (already seeded with x_proj + b_h) -> tanh -> STG fp32 hout
// + 4x STS.16 bf16 into the other buffer. One __syncthreads per step.

__device__ __forceinline__ uint32_t b_addr(int j, int n) {
    return (uint32_t)((j >> 4) * 256 + (((n << 2) | ((j & 7) >> 1)) << 3)
                      + (((j >> 3) & 1) << 2) + ((j & 1) << 1));
}

__device__ __forceinline__ unsigned bf2(float a, float b) {
    __nv_bfloat162 t = __floats2bfloat162_rn(a, b);
    return *(unsigned*)&t;
}

__global__ void __launch_bounds__(512, 1) k_rnn(const void* __restrict__ xraw,
        const float* __restrict__ hidden, const float* __restrict__ Wh,
        const float* __restrict__ bh, float* __restrict__ dout, int write_final) {
    __shared__ __align__(16) char bbuf[2][4096];
    const int tid = threadIdx.x;
    const int wid = tid >> 5, lane = tid & 31;
    const int g = lane >> 2, tt = lane & 3;
    const int j0 = wid * 16 + g, j1 = j0 + 8;   // my two output rows
    const int n0 = 2 * tt, n1 = n0 + 1;         // my two batch columns
    const int B0 = blockIdx.x * NB;
    const int is32 = g_x_is32;
    const int* x32       = (const int*)xraw;
    const long long* x64 = (const long long*)xraw;

    // ---- load W_h as A fragments into registers (one-time) ----
    unsigned wf[16][4];
    #pragma unroll
    for (int kk = 0; kk < 16; kk++) {
        int k = kk * 16 + 2 * tt;
        float2 p0 = *(const float2*)(Wh + j0 * Hn + k);
        float2 p1 = *(const float2*)(Wh + j1 * Hn + k);
        float2 p2 = *(const float2*)(Wh + j0 * Hn + k + 8);
        float2 p3 = *(const float2*)(Wh + j1 * Hn + k + 8);
        wf[kk][0] = bf2(p0.x, p0.y);
        wf[kk][1] = bf2(p1.x, p1.y);
        wf[kk][2] = bf2(p2.x, p2.y);
        wf[kk][3] = bf2(p3.x, p3.y);
    }

    // ---- initial B fill from hidden (fp32 -> bf16, fragment layout) ----
    for (int p = tid; p < Hn * NB; p += 512) {
        int j = p >> 3, n = p & 7;
        float hv = hidden[(B0 + n) * Hn + j];
        *(__nv_bfloat16*)(bbuf[0] + b_addr(j, n)) = __float2bfloat16_rn(hv);
    }

    const float bh0 = bh[j0], bh1 = bh[j1];

    // hout base for (n0, j0); others at fixed offsets (+Ln*Hn for n+1, +8 for j+8)
    size_t base = ((size_t)(B0 + n0) * Ln) * Hn + j0;
    const size_t NSTRIDE = (size_t)Ln * Hn;

    // prefetch tokens for t=0
    int tokA = is32 ? x32[(B0 + n0) * Ln] : (int)x64[(B0 + n0) * Ln];
    int tokB = is32 ? x32[(B0 + n1) * Ln] : (int)x64[(B0 + n1) * Ln];

    __syncthreads();

    float h00 = 0.f, h01 = 0.f, h10 = 0.f, h11 = 0.f;
    for (int t = 0; t < Ln; t++) {
        // seed accumulators with x_proj + b_h (xp loads overlap the MMA chain)
        float c0 = g_proj[tokA * Hn + j0] + bh0;   // (j0, n0)
        float c1 = g_proj[tokB * Hn + j0] + bh0;   // (j0, n1)
        float c2 = g_proj[tokA * Hn + j1] + bh1;   // (j1, n0)
        float c3 = g_proj[tokB * Hn + j1] + bh1;   // (j1, n1)

        // prefetch next step's tokens
        if (t + 1 < Ln) {
            tokA = is32 ? x32[(B0 + n0) * Ln + t + 1] : (int)x64[(B0 + n0) * Ln + t + 1];
            tokB = is32 ? x32[(B0 + n1) * Ln + t + 1] : (int)x64[(B0 + n1) * Ln + t + 1];
        }

        const char* cb = bbuf[t & 1];
        #pragma unroll
        for (int kk = 0; kk < 16; kk++) {
            unsigned long long bb = *(const unsigned long long*)(cb + kk * 256 + lane * 8);
            unsigned b0 = (unsigned)bb, b1 = (unsigned)(bb >> 32);
            asm volatile(
                "mma.sync.aligned.m16n8k16.row.col.f32.bf16.bf16.f32 "
                "{%0,%1,%2,%3}, {%4,%5,%6,%7}, {%8,%9}, {%0,%1,%2,%3};"
                : "+f"(c0), "+f"(c1), "+f"(c2), "+f"(c3)
                : "r"(wf[kk][0]), "r"(wf[kk][1]), "r"(wf[kk][2]), "r"(wf[kk][3]),
                  "r"(b0), "r"(b1));
        }

        h00 = tanh_fast(c0);
        h01 = tanh_fast(c1);
        h10 = tanh_fast(c2);
        h11 = tanh_fast(c3);

        // fp32 hidden states to gmem
        g_hout[base]               = h00;
        g_hout[base + NSTRIDE]     = h01;
        g_hout[base + 8]           = h10;
        g_hout[base + NSTRIDE + 8] = h11;
        base += Hn;

        // bf16 h into the other buffer (next step's B operand)
        char* nb = bbuf[(t & 1) ^ 1];
        *(__nv_bfloat16*)(nb + b_addr(j0, n0)) = __float2bfloat16_rn(h00);
        *(__nv_bfloat16*)(nb + b_addr(j0, n1)) = __float2bfloat16_rn(h01);
        *(__nv_bfloat16*)(nb + b_addr(j1, n0)) = __float2bfloat16_rn(h10);
        *(__nv_bfloat16*)(nb + b_addr(j1, n1)) = __float2bfloat16_rn(h11);

        __syncthreads();
    }

    if (write_final) {
        float* fh = dout + (size_t)Bn * Ln * Vn;
        fh[(B0 + n0) * Hn + j0] = h00;
        fh[(B0 + n1) * Hn + j0] = h01;
        fh[(B0 + n0) * Hn + j1] = h10;
        fh[(B0 + n1) * Hn + j1] = h11;
    }
}

// ---------------- logits GEMM (R9 version, f32x2) ----------------
#define LOG_SMEM (65536 + 64 * 260 * 4)

__global__ void __launch_bounds__(256, 1) k_logits(const float* __restrict__ fcw,
        const float* __restrict__ fcb, float* __restrict__ out) {
    extern __shared__ char smem[];
    float* fT  = (float*)smem;              // [256][64]  fT[k][v] = fcw[v][k]
    float* hsm = (float*)(smem + 65536);    // [64][260]
    const int tid = threadIdx.x;
    const int tx = tid & 15, ty = tid >> 4;

    for (int p = tid; p < Vn * Hn; p += 256) {
        int v = p & 63, k = p >> 6;
        fT[k * 64 + v] = fcw[v * Hn + k];
    }
    float4 bias = *(const float4*)(fcb + 4 * tx);
    __syncthreads();

    const int ntiles = (Bn * Ln) / 64;      // 4096
    for (int tile = blockIdx.x; tile < ntiles; tile += gridDim.x) {
        const float4* src = (const float4*)(g_hout + (size_t)tile * 64 * Hn);
        for (int p = tid; p < 64 * 64; p += 256) {
            int row = p >> 6, kc = p & 63;
            *(float4*)(hsm + row * 260 + 4 * kc) = src[p];
        }
        __syncthreads();

        unsigned long long acc[4][2];
        #pragma unroll
        for (int r = 0; r < 4; r++) { acc[r][0] = 0ull; acc[r][1] = 0ull; }

        #pragma unroll 8
        for (int k = 0; k < Hn; k++) {
            ulonglong2 bp = *(const ulonglong2*)(fT + k * 64 + 4 * tx);
            unsigned long long a0 = dup2f(hsm[(4 * ty + 0) * 260 + k]);
            unsigned long long a1 = dup2f(hsm[(4 * ty + 1) * 260 + k]);
            unsigned long long a2 = dup2f(hsm[(4 * ty + 2) * 260 + k]);
            unsigned long long a3 = dup2f(hsm[(4 * ty + 3) * 260 + k]);
            ffma2(acc[0][0], a0, bp.x); ffma2(acc[0][1], a0, bp.y);
            ffma2(acc[1][0], a1, bp.x); ffma2(acc[1][1], a1, bp.y);
            ffma2(acc[2][0], a2, bp.x); ffma2(acc[2][1], a2, bp.y);
            ffma2(acc[3][0], a3, bp.x); ffma2(acc[3][1], a3, bp.y);
        }
        #pragma unroll
        for (int r = 0; r < 4; r++) {
            float2 c01 = unpack2(acc[r][0]);
            float2 c23 = unpack2(acc[r][1]);
            float4 o;
            o.x = c01.x + bias.x; o.y = c01.y + bias.y;
            o.z = c23.x + bias.z; o.w = c23.y + bias.w;
            *(float4*)(out + ((size_t)tile * 64 + 4 * ty + r) * 64 + 4 * tx) = o;
        }
        __syncthreads();
    }
}

// ---------------- launch ----------------
extern "C" void kernel_launch(void* const* d_in, const int* in_sizes, int n_in,
                              void* d_out, int out_size) {
    const void*  x      = d_in[0];
    const float* hidden = (const float*)d_in[1];
    const float* emb    = (const float*)d_in[2];
    const float* We     = (const float*)d_in[3];
    const float* be     = (const float*)d_in[4];
    const float* Wh     = (const float*)d_in[5];
    const float* bhp    = (const float*)d_in[6];
    const float* fcw    = (const float*)d_in[7];
    const float* fcb    = (const float*)d_in[8];
    float* out = (float*)d_out;

    cudaFuncSetAttribute(k_logits, cudaFuncAttributeMaxDynamicSharedMemorySize, LOG_SMEM);

    k_reset<<<1, 1>>>();
    k_detect<<<(Bn * Ln / 2 + 255) / 256, 256>>>((const unsigned int*)x);
    k_proj<<<Vn, Hn>>>(emb, We, be);

    int write_final = (out_size >= Bn * Ln * Vn + Bn * Hn) ? 1 : 0;
    k_rnn<<<NCTA, 512>>>(x, hidden, Wh, bhp, out, write_final);
    k_logits<<<148, 256, LOG_SMEM>>>(fcw, fcb, out);
}

// round 13
// speedup vs baseline: 3.6407x; 1.0804x over previous
#include <cuda_runtime.h>
#include <cuda_bf16.h>
#include <cstdint>

#define Bn 256
#define Ln 1024
#define En 128
#define Hn 256
#define Vn 64
#define NB 8                  // batches per CTA (MMA N)
#define NCTA (Bn / NB)        // 32 CTAs

// ---- device-global scratch (no allocations allowed) ----
__device__ float g_proj[Vn * Hn];                    // token -> x_proj row (b_e folded in)
__device__ float g_hout[(size_t)Bn * Ln * Hn];       // all hidden states, 268MB
__device__ int   g_x_is32;

__device__ __forceinline__ float tanh_hw(float x) {
    float r;
    asm("tanh.approx.f32 %0, %1;" : "=f"(r) : "f"(x));
    return r;
}
__device__ __forceinline__ uint32_t f2tf32(float f) {
    uint32_t u;
    asm("cvt.rna.tf32.f32 %0, %1;" : "=r"(u) : "f"(f));
    return u;
}

// ---------------- dtype detection ----------------
__global__ void k_reset() { g_x_is32 = 0; }

__global__ void k_detect(const unsigned int* __restrict__ xw) {
    int i = blockIdx.x * blockDim.x + threadIdx.x;
    int idx = 2 * i + 1;
    if (idx < Bn * Ln) {
        if (xw[idx] != 0u) g_x_is32 = 1;   // int64 high halves all zero (vals 0..63)
    }
}

// ---------------- projection table ----------------
__global__ void k_proj(const float* __restrict__ emb, const float* __restrict__ We,
                       const float* __restrict__ be) {
    __shared__ float es[En];
    int v = blockIdx.x, j = threadIdx.x;
    if (j < En) es[j] = emb[v * En + j];
    __syncthreads();
    float acc = 0.f;
    #pragma unroll
    for (int e = 0; e < En; e++) acc = fmaf(es[e], We[j * En + e], acc);
    g_proj[v * Hn + j] = acc + be[j];
}

// ---------------- recurrence on HMMA (mma.sync m16n8k16 bf16) ----------------
// 32 CTAs x 512 threads (16 warps). CTA owns batches [8c, 8c+8) end-to-end.
// Warp w owns output rows [16w, 16w+16). W_h in registers as A fragments.
// h double-buffered in smem in exact B-fragment layout.
// R13: 4 independent accumulator groups (chain depth 16 -> 4); xp+bh added
// after the chain; HW tanh.approx.

__device__ __forceinline__ uint32_t b_addr(int j, int n) {
    return (uint32_t)((j >> 4) * 256 + (((n << 2) | ((j & 7) >> 1)) << 3)
                      + (((j >> 3) & 1) << 2) + ((j & 1) << 1));
}

__device__ __forceinline__ unsigned bf2(float a, float b) {
    __nv_bfloat162 t = __floats2bfloat162_rn(a, b);
    return *(unsigned*)&t;
}

__global__ void __launch_bounds__(512, 1) k_rnn(const void* __restrict__ xraw,
        const float* __restrict__ hidden, const float* __restrict__ Wh,
        const float* __restrict__ bh, float* __restrict__ dout, int write_final) {
    __shared__ __align__(16) char bbuf[2][4096];
    const int tid = threadIdx.x;
    const int wid = tid >> 5, lane = tid & 31;
    const int g = lane >> 2, tt = lane & 3;
    const int j0 = wid * 16 + g, j1 = j0 + 8;   // my two output rows
    const int n0 = 2 * tt, n1 = n0 + 1;         // my two batch columns
    const int B0 = blockIdx.x * NB;
    const int is32 = g_x_is32;
    const int* x32       = (const int*)xraw;
    const long long* x64 = (const long long*)xraw;

    // ---- load W_h as A fragments into registers (one-time) ----
    unsigned wf[16][4];
    #pragma unroll
    for (int kk = 0; kk < 16; kk++) {
        int k = kk * 16 + 2 * tt;
        float2 p0 = *(const float2*)(Wh + j0 * Hn + k);
        float2 p1 = *(const float2*)(Wh + j1 * Hn + k);
        float2 p2 = *(const float2*)(Wh + j0 * Hn + k + 8);
        float2 p3 = *(const float2*)(Wh + j1 * Hn + k + 8);
        wf[kk][0] = bf2(p0.x, p0.y);
        wf[kk][1] = bf2(p1.x, p1.y);
        wf[kk][2] = bf2(p2.x, p2.y);
        wf[kk][3] = bf2(p3.x, p3.y);
    }

    // ---- initial B fill from hidden (fp32 -> bf16, fragment layout) ----
    for (int p = tid; p < Hn * NB; p += 512) {
        int j = p >> 3, n = p & 7;
        float hv = hidden[(B0 + n) * Hn + j];
        *(__nv_bfloat16*)(bbuf[0] + b_addr(j, n)) = __float2bfloat16_rn(hv);
    }

    const float bh0 = bh[j0], bh1 = bh[j1];

    size_t base = ((size_t)(B0 + n0) * Ln) * Hn + j0;
    const size_t NSTRIDE = (size_t)Ln * Hn;

    int tokA = is32 ? x32[(B0 + n0) * Ln] : (int)x64[(B0 + n0) * Ln];
    int tokB = is32 ? x32[(B0 + n1) * Ln] : (int)x64[(B0 + n1) * Ln];

    __syncthreads();

    float h00 = 0.f, h01 = 0.f, h10 = 0.f, h11 = 0.f;
    for (int t = 0; t < Ln; t++) {
        // xp loads overlap the MMA chain (added after accumulation)
        float xp00 = g_proj[tokA * Hn + j0];
        float xp01 = g_proj[tokB * Hn + j0];
        float xp10 = g_proj[tokA * Hn + j1];
        float xp11 = g_proj[tokB * Hn + j1];

        if (t + 1 < Ln) {
            tokA = is32 ? x32[(B0 + n0) * Ln + t + 1] : (int)x64[(B0 + n0) * Ln + t + 1];
            tokB = is32 ? x32[(B0 + n1) * Ln + t + 1] : (int)x64[(B0 + n1) * Ln + t + 1];
        }

        // 4 independent accumulator groups: chain depth 16 -> 4
        float acc[4][4];
        #pragma unroll
        for (int gaci = 0; gaci < 4; gaci++)
            #pragma unroll
            for (int e = 0; e < 4; e++) acc[gaci][e] = 0.f;

        const char* cb = bbuf[t & 1];
        #pragma unroll
        for (int kk = 0; kk < 16; kk++) {
            unsigned long long bb = *(const unsigned long long*)(cb + kk * 256 + lane * 8);
            unsigned b0 = (unsigned)bb, b1 = (unsigned)(bb >> 32);
            float* c = acc[kk & 3];
            asm volatile(
                "mma.sync.aligned.m16n8k16.row.col.f32.bf16.bf16.f32 "
                "{%0,%1,%2,%3}, {%4,%5,%6,%7}, {%8,%9}, {%0,%1,%2,%3};"
                : "+f"(c[0]), "+f"(c[1]), "+f"(c[2]), "+f"(c[3])
                : "r"(wf[kk][0]), "r"(wf[kk][1]), "r"(wf[kk][2]), "r"(wf[kk][3]),
                  "r"(b0), "r"(b1));
        }

        float c0 = (acc[0][0] + acc[1][0]) + (acc[2][0] + acc[3][0]) + (xp00 + bh0);
        float c1 = (acc[0][1] + acc[1][1]) + (acc[2][1] + acc[3][1]) + (xp01 + bh0);
        float c2 = (acc[0][2] + acc[1][2]) + (acc[2][2] + acc[3][2]) + (xp10 + bh1);
        float c3 = (acc[0][3] + acc[1][3]) + (acc[2][3] + acc[3][3]) + (xp11 + bh1);

        h00 = tanh_hw(c0);
        h01 = tanh_hw(c1);
        h10 = tanh_hw(c2);
        h11 = tanh_hw(c3);

        // bf16 h into the other buffer first (critical path to next step)
        char* nb = bbuf[(t & 1) ^ 1];
        *(__nv_bfloat16*)(nb + b_addr(j0, n0)) = __float2bfloat16_rn(h00);
        *(__nv_bfloat16*)(nb + b_addr(j0, n1)) = __float2bfloat16_rn(h01);
        *(__nv_bfloat16*)(nb + b_addr(j1, n0)) = __float2bfloat16_rn(h10);
        *(__nv_bfloat16*)(nb + b_addr(j1, n1)) = __float2bfloat16_rn(h11);

        // fp32 hidden states to gmem (off critical path)
        g_hout[base]               = h00;
        g_hout[base + NSTRIDE]     = h01;
        g_hout[base + 8]           = h10;
        g_hout[base + NSTRIDE + 8] = h11;
        base += Hn;

        __syncthreads();
    }

    if (write_final) {
        float* fh = dout + (size_t)Bn * Ln * Vn;
        fh[(B0 + n0) * Hn + j0] = h00;
        fh[(B0 + n1) * Hn + j0] = h01;
        fh[(B0 + n0) * Hn + j1] = h10;
        fh[(B0 + n1) * Hn + j1] = h11;
    }
}

// ---------------- logits GEMM on tf32 HMMA (mma.sync m16n8k8) ----------------
// logits[r][v] = sum_k hout[r][k] * fcw[v][k] + fcb[v]
// 148 persistent CTAs x 256 threads (8 warps). Tile = 64 rows x 64 V x K=256.
// Warp w owns n-strip [8w, 8w+8) x 4 m16 tiles. Operands tf32 (cvt.rna).
// smem: fT[k=256][v=64] pad 72 (8-bank skew), hsm[64][k=256] pad 260 (4-bank skew).
#define FT_PAD 72
#define HS_PAD 260
#define LOG_SMEM (256 * FT_PAD * 4 + 64 * HS_PAD * 4)

__global__ void __launch_bounds__(256, 1) k_logits(const float* __restrict__ fcw,
        const float* __restrict__ fcb, float* __restrict__ out) {
    extern __shared__ char smem[];
    uint32_t* fT  = (uint32_t*)smem;                          // [256][72]
    uint32_t* hsm = (uint32_t*)(smem + 256 * FT_PAD * 4);     // [64][260]
    const int tid = threadIdx.x;
    const int wid = tid >> 5, lane = tid & 31;
    const int g = lane >> 2, tt = lane & 3;
    const int nb = wid * 8;

    // fill fT[k][v] = tf32(fcw[v][k]) — coalesced LDG (k fastest)
    for (int p = tid; p < Vn * Hn; p += 256) {
        int v = p >> 8, k = p & 255;
        fT[k * FT_PAD + v] = f2tf32(fcw[v * Hn + k]);
    }
    const float2 bias = make_float2(fcb[nb + 2 * tt], fcb[nb + 2 * tt + 1]);
    __syncthreads();

    const int ntiles = (Bn * Ln) / 64;      // 4096
    for (int tile = blockIdx.x; tile < ntiles; tile += gridDim.x) {
        const float4* src = (const float4*)(g_hout + (size_t)tile * 64 * Hn);
        for (int p = tid; p < 64 * 64; p += 256) {
            int row = p >> 6, kc = p & 63;
            float4 v = src[row * 64 + kc];
            uint4 u;
            u.x = f2tf32(v.x); u.y = f2tf32(v.y);
            u.z = f2tf32(v.z); u.w = f2tf32(v.w);
            *(uint4*)(hsm + row * HS_PAD + 4 * kc) = u;
        }
        __syncthreads();

        float c[4][4];
        #pragma unroll
        for (int mt = 0; mt < 4; mt++)
            #pragma unroll
            for (int e = 0; e < 4; e++) c[mt][e] = 0.f;

        #pragma unroll 4
        for (int ks = 0; ks < 32; ks++) {
            int k0 = 8 * ks;
            uint32_t b0 = fT[(k0 + tt) * FT_PAD + nb + g];
            uint32_t b1 = fT[(k0 + tt + 4) * FT_PAD + nb + g];
            #pragma unroll
            for (int mt = 0; mt < 4; mt++) {
                int r0 = mt * 16 + g;
                uint32_t a0 = hsm[r0 * HS_PAD + k0 + tt];
                uint32_t a1 = hsm[(r0 + 8) * HS_PAD + k0 + tt];
                uint32_t a2 = hsm[r0 * HS_PAD + k0 + tt + 4];
                uint32_t a3 = hsm[(r0 + 8) * HS_PAD + k0 + tt + 4];
                asm volatile(
                    "mma.sync.aligned.m16n8k8.row.col.f32.tf32.tf32.f32 "
                    "{%0,%1,%2,%3}, {%4,%5,%6,%7}, {%8,%9}, {%0,%1,%2,%3};"
                    : "+f"(c[mt][0]), "+f"(c[mt][1]), "+f"(c[mt][2]), "+f"(c[mt][3])
                    : "r"(a0), "r"(a1), "r"(a2), "r"(a3), "r"(b0), "r"(b1));
            }
        }

        #pragma unroll
        for (int mt = 0; mt < 4; mt++) {
            int r0 = mt * 16 + g;
            size_t o0 = ((size_t)tile * 64 + r0) * 64 + nb + 2 * tt;
            *(float2*)(out + o0) = make_float2(c[mt][0] + bias.x, c[mt][1] + bias.y);
            *(float2*)(out + o0 + 8 * 64) = make_float2(c[mt][2] + bias.x, c[mt][3] + bias.y);
        }
        __syncthreads();
    }
}

// ---------------- launch ----------------
extern "C" void kernel_launch(void* const* d_in, const int* in_sizes, int n_in,
                              void* d_out, int out_size) {
    const void*  x      = d_in[0];
    const float* hidden = (const float*)d_in[1];
    const float* emb    = (const float*)d_in[2];
    const float* We     = (const float*)d_in[3];
    const float* be     = (const float*)d_in[4];
    const float* Wh     = (const float*)d_in[5];
    const float* bhp    = (const float*)d_in[6];
    const float* fcw    = (const float*)d_in[7];
    const float* fcb    = (const float*)d_in[8];
    float* out = (float*)d_out;

    cudaFuncSetAttribute(k_logits, cudaFuncAttributeMaxDynamicSharedMemorySize, LOG_SMEM);

    k_reset<<<1, 1>>>();
    k_detect<<<(Bn * Ln / 2 + 255) / 256, 256>>>((const unsigned int*)x);
    k_proj<<<Vn, Hn>>>(emb, We, be);

    int write_final = (out_size >= Bn * Ln * Vn + Bn * Hn) ? 1 : 0;
    k_rnn<<<NCTA, 512>>>(x, hidden, Wh, bhp, out, write_final);
    k_logits<<<148, 256, LOG_SMEM>>>(fcw, fcb, out);
}